// round 14
// baseline (speedup 1.0000x reference)
#include <cuda_runtime.h>
#include <cuda_bf16.h>
#include <cuda_fp16.h>
#include <cstdint>

#define EPSN 1e-5f

__device__ float g_h1[32*16*128*128];
__device__ float g_enc[32*64*64*64];
__device__ float g_dec_in[32*64*64*64];
__device__ float g_d1[32*16*128*128];
__device__ float g_bn_s[16], g_bn_q[16];
__device__ float g_m2s[2048], g_q2s[2048];
__device__ float g_loss;
__device__ __nv_bfloat16 g_cb_bf16[6*512*64];
__device__ float g_cbnorm[6*512];
__device__ float g_bmax[6];

extern __shared__ float dynsm[];

typedef unsigned long long ull;

#define FMA2(acc, a, b_) asm("fma.rn.f32x2 %0, %1, %2, %3;" : "=l"(acc) : "l"(a), "l"(b_), "l"(acc))

__device__ __forceinline__ float2 unpack2(ull p){
    float2 f; asm("mov.b64 {%0,%1}, %2;" : "=f"(f.x), "=f"(f.y) : "l"(p)); return f;
}
__device__ __forceinline__ ull pack2(float lo, float hi){
    ull p; asm("mov.b64 %0, {%1,%2};" : "=l"(p) : "f"(lo), "f"(hi)); return p;
}
__device__ __forceinline__ float warpsum(float v){
    #pragma unroll
    for (int o = 16; o; o >>= 1) v += __shfl_down_sync(0xffffffffu, v, o);
    return v;
}
__device__ __forceinline__ uint32_t smem_u32(const void* p){
    uint32_t a;
    asm("{ .reg .u64 t; cvta.to.shared.u64 t, %1; cvt.u32.u64 %0, t; }" : "=r"(a) : "l"(p));
    return a;
}

#define SWZ128(b) ((b) ^ (((b) >> 3) & 0x70))

__device__ __forceinline__ void mma16816(float c[4], const uint32_t a[4],
                                         uint32_t b0, uint32_t b1){
    asm volatile(
        "mma.sync.aligned.m16n8k16.row.col.f32.bf16.bf16.f32 "
        "{%0,%1,%2,%3}, {%4,%5,%6,%7}, {%8,%9}, {%0,%1,%2,%3};"
        : "+f"(c[0]), "+f"(c[1]), "+f"(c[2]), "+f"(c[3])
        : "r"(a[0]), "r"(a[1]), "r"(a[2]), "r"(a[3]), "r"(b0), "r"(b1));
}
__device__ __forceinline__ void ldsm_x4(uint32_t r[4], uint32_t addr){
    asm volatile("ldmatrix.sync.aligned.m8n8.x4.shared.b16 {%0,%1,%2,%3}, [%4];"
        : "=r"(r[0]), "=r"(r[1]), "=r"(r[2]), "=r"(r[3]) : "r"(addr));
}

#define UPD(m1,i1,m2,s,k) do{ \
    if ((s) < (m1)){ (m2)=(m1); (m1)=(s); (i1)=(k); } \
    else if ((s) < (m2)){ (m2)=(s); } }while(0)

#define MERGE(m1,i1,m2,om1,oi1,om2) do{ \
    if ((om1) < (m1)){ (m2) = fminf((m1), (om2)); (m1)=(om1); (i1)=(oi1); } \
    else if ((om1) < (m2)){ (m2)=(om1); } }while(0)

// ---------------- conv1 + cbprep + zeroing -----------------------------------
__global__ __launch_bounds__(512) void k_conv1x(const float* __restrict__ x,
                                                const float* __restrict__ w,
                                                const float* __restrict__ b,
                                                const float* __restrict__ cb){
    __shared__ float wsm[48][16];
    __shared__ float mx[16];
    int tid = threadIdx.x;
    for (int i = tid; i < 768; i += 512){
        int co = i / 48, idx = i % 48;
        wsm[idx][co] = w[i];
    }
    __syncthreads();
    int n     = blockIdx.x >> 4;
    int chunk = blockIdx.x & 15;
    int row = tid >> 6, col = tid & 63;
    int oh = chunk*8 + row;
    ull accA[8], accB[8];
    #pragma unroll
    for (int j = 0; j < 8; j++){ accA[j] = pack2(b[2*j], b[2*j+1]); accB[j] = accA[j]; }
    const float* xn = x + (size_t)n * 3 * 65536;
    for (int ci = 0; ci < 3; ci++){
        #pragma unroll
        for (int kh = 0; kh < 4; kh++){
            int ih = 2*oh + kh - 1;
            if ((unsigned)ih >= 256u) continue;
            const float* rowp = xn + (ci*256 + ih)*256;
            #pragma unroll
            for (int kw = 0; kw < 4; kw++){
                int iwA = 2*col + kw - 1;
                int iwB = iwA + 128;
                float vA = ((unsigned)iwA < 256u) ? rowp[iwA] : 0.f;
                float vB = ((unsigned)iwB < 256u) ? rowp[iwB] : 0.f;
                ull vA2 = pack2(vA, vA), vB2 = pack2(vB, vB);
                const ull* wr = (const ull*)wsm[ci*16 + kh*4 + kw];
                #pragma unroll
                for (int j = 0; j < 8; j++){
                    FMA2(accA[j], vA2, wr[j]);
                    FMA2(accB[j], vB2, wr[j]);
                }
            }
        }
    }
    float* outp = g_h1 + (size_t)n * 16 * 16384 + oh*128 + col;
    #pragma unroll
    for (int j = 0; j < 8; j++){
        float2 fA = unpack2(accA[j]), fB = unpack2(accB[j]);
        outp[(size_t)(2*j  ) * 16384]      = fA.x;
        outp[(size_t)(2*j+1) * 16384]      = fA.y;
        outp[(size_t)(2*j  ) * 16384 + 64] = fB.x;
        outp[(size_t)(2*j+1) * 16384 + 64] = fB.y;
    }
    if (blockIdx.x < 6){
        int st = blockIdx.x, k = tid;
        const float* row2 = cb + (size_t)(st*512 + k) * 64;
        float s = 0.f;
        __nv_bfloat162* dst = (__nv_bfloat162*)g_cb_bf16 + (size_t)(st*512 + k) * 32;
        #pragma unroll
        for (int j = 0; j < 32; j++){
            float a = row2[2*j], b2 = row2[2*j+1];
            s = fmaf(a, a, fmaf(b2, b2, s));
            dst[j] = __float22bfloat162_rn(make_float2(a, b2));
        }
        g_cbnorm[st*512 + k] = s;
        float m = s;
        #pragma unroll
        for (int o = 16; o; o >>= 1) m = fmaxf(m, __shfl_down_sync(0xffffffffu, m, o));
        int wid = k >> 5;
        if ((k & 31) == 0) mx[wid] = m;
        __syncthreads();
        if (k == 0){
            float M = 0.f;
            #pragma unroll
            for (int i = 0; i < 16; i++) M = fmaxf(M, mx[i]);
            g_bmax[st] = sqrtf(M);
        }
    } else if (blockIdx.x < 14){
        int i = (blockIdx.x - 6) * 512 + tid;
        if (i < 2048) g_m2s[i] = 0.f;
        else          g_q2s[i - 2048] = 0.f;
    } else if (blockIdx.x == 14){
        if (tid == 0) g_loss = 0.f;
        if (tid < 16){ g_bn_s[tid] = 0.f; g_bn_q[tid] = 0.f; }
    }
}

// ---------------- fused per-plane stats + normalize + relu (g_h1) -----------
__global__ __launch_bounds__(512) void k_statsnorm(int mode){
    int p = blockIdx.x;
    float* sp; int plane;
    if (mode == 0){ sp = g_h1 + (size_t)p*16384; plane = 16384; }
    else          { sp = g_enc + (size_t)p*4096; plane = 4096; }
    float s = 0.f, q = 0.f;
    float4* sp4 = (float4*)sp;
    for (int i = threadIdx.x; i < plane/4; i += 512){
        float4 xv = sp4[i];
        s += xv.x + xv.y + xv.z + xv.w;
        q = fmaf(xv.x, xv.x, fmaf(xv.y, xv.y, fmaf(xv.z, xv.z, fmaf(xv.w, xv.w, q))));
    }
    __shared__ float rsum[16], rsq[16];
    __shared__ float sm_m, sm_r;
    s = warpsum(s); q = warpsum(q);
    int wid = threadIdx.x >> 5, lane = threadIdx.x & 31;
    if (lane == 0){ rsum[wid] = s; rsq[wid] = q; }
    __syncthreads();
    if (threadIdx.x == 0){
        float S = 0.f, Q = 0.f;
        #pragma unroll
        for (int i = 0; i < 16; i++){ S += rsum[i]; Q += rsq[i]; }
        float inv = 1.f / (float)plane;
        float mm = S * inv;
        sm_m = mm;
        sm_r = rsqrtf(Q * inv - mm*mm + EPSN);
    }
    __syncthreads();
    float m = sm_m, r = sm_r;
    for (int i = threadIdx.x; i < plane/4; i += 512){
        float4 xv = sp4[i];
        xv.x = fmaxf((xv.x - m) * r, 0.f);
        xv.y = fmaxf((xv.y - m) * r, 0.f);
        xv.z = fmaxf((xv.z - m) * r, 0.f);
        xv.w = fmaxf((xv.w - m) * r, 0.f);
        sp4[i] = xv;
    }
}

// ---------------- conv2 + fused enc stats ------------------------------------
__global__ __launch_bounds__(512) void k_conv2s(const float* __restrict__ w,
                                                const float* __restrict__ b){
    float* wsm = dynsm;
    float* tile = dynsm + 16384;
    int tid = threadIdx.x;
    for (int i = tid; i < 16384; i += 512){
        int co = i >> 8, idx = i & 255;
        wsm[idx*64 + co] = w[i];
    }
    int n   = blockIdx.x >> 3;
    int oh0 = (blockIdx.x & 7) << 3;
    int ihg0 = 2*oh0 - 1;
    const float* hn = g_h1 + (size_t)n * 16 * 16384;
    for (int i = tid; i < 16*18*132; i += 512){
        int ci = i / 2376, rem = i % 2376;
        int r = rem / 132, c = rem % 132;
        int ihg = ihg0 + r, iwg = c - 1;
        float v = 0.f;
        if ((unsigned)ihg < 128u && (unsigned)iwg < 128u)
            v = hn[(ci*128 + ihg)*128 + iwg];
        tile[i] = v;
    }
    __syncthreads();
    int rowl = tid >> 6, coq = (tid >> 4) & 3, colb = tid & 15;
    ull acc[4][8];
    #pragma unroll
    for (int px = 0; px < 4; px++)
        #pragma unroll
        for (int j = 0; j < 8; j++)
            acc[px][j] = pack2(b[16*coq + 2*j], b[16*coq + 2*j + 1]);
    for (int ci = 0; ci < 16; ci++){
        const float* tci = tile + ci*2376;
        #pragma unroll
        for (int kh = 0; kh < 4; kh++){
            const float* trow = tci + (2*rowl + kh)*132 + 2*colb;
            #pragma unroll
            for (int kw = 0; kw < 4; kw++){
                float v0 = trow[kw];
                float v1 = trow[kw + 32];
                float v2 = trow[kw + 64];
                float v3 = trow[kw + 96];
                ull p0 = pack2(v0, v0), p1 = pack2(v1, v1);
                ull p2 = pack2(v2, v2), p3 = pack2(v3, v3);
                const ull* wr = (const ull*)(wsm + (ci*16 + kh*4 + kw)*64 + 16*coq);
                #pragma unroll
                for (int j = 0; j < 8; j++){
                    ull ww = wr[j];
                    FMA2(acc[0][j], p0, ww);
                    FMA2(acc[1][j], p1, ww);
                    FMA2(acc[2][j], p2, ww);
                    FMA2(acc[3][j], p3, ww);
                }
            }
        }
    }
    int oh = oh0 + rowl;
    float* outp = g_enc + (size_t)n * 64 * 4096 + (size_t)(16*coq) * 4096 + oh*64 + colb;
    #pragma unroll
    for (int px = 0; px < 4; px++){
        #pragma unroll
        for (int j = 0; j < 8; j++){
            float2 f = unpack2(acc[px][j]);
            outp[(size_t)(2*j  ) * 4096 + px*16] = f.x;
            outp[(size_t)(2*j+1) * 4096 + px*16] = f.y;
        }
    }
    #pragma unroll
    for (int j = 0; j < 8; j++){
        float s0 = 0.f, s1 = 0.f, q0 = 0.f, q1 = 0.f;
        #pragma unroll
        for (int px = 0; px < 4; px++){
            float2 f = unpack2(acc[px][j]);
            s0 += f.x; s1 += f.y;
            q0 = fmaf(f.x, f.x, q0);
            q1 = fmaf(f.y, f.y, q1);
        }
        #pragma unroll
        for (int o = 8; o; o >>= 1){
            s0 += __shfl_down_sync(0xffffffffu, s0, o, 16);
            s1 += __shfl_down_sync(0xffffffffu, s1, o, 16);
            q0 += __shfl_down_sync(0xffffffffu, q0, o, 16);
            q1 += __shfl_down_sync(0xffffffffu, q1, o, 16);
        }
        if ((tid & 15) == 0){
            int co = 16*coq + 2*j;
            atomicAdd(&g_m2s[n*64 + co],     s0);
            atomicAdd(&g_m2s[n*64 + co + 1], s1);
            atomicAdd(&g_q2s[n*64 + co],     q0);
            atomicAdd(&g_q2s[n*64 + co + 1], q1);
        }
    }
}

// ---------------- RVQ v6: 256 thr / 8 MMA warps, 2 blocks/SM -----------------
#define R6_CB   0        // 32768
#define R6_A    32768    // 8192
#define R6_NRM  40960    // 2048
#define R6_MB   43008    // 6144 : minbuf [8 w][64 rows] stride 12 / msm+rsm
#define R6_SC   49152    // 66304
#define R6_RED  115456   // 64
#define RVQ6_SMEM 115520

__global__ __launch_bounds__(256, 2) void k_rvq6(const float* __restrict__ cb){
    char* smc = (char*)dynsm;
    float* norms = (float*)(smc + R6_NRM);
    float* msm   = (float*)(smc + R6_MB);
    float* rsm   = (float*)(smc + R6_MB + 256);
    float* red   = (float*)(smc + R6_RED);
    uint32_t sb = smem_u32(smc);
    int tid = threadIdx.x;
    int w = tid >> 5, l = tid & 31;
    int g = l >> 2, tig = l & 3;
    bool owner = tid < 64;

    int n   = blockIdx.x >> 6;
    int pix = ((blockIdx.x & 63) << 6) + (tid & 63);
    const float* encp = g_enc + (size_t)n * 64 * 4096 + pix;

    if (tid < 64){
        float m = g_m2s[n*64 + tid] * (1.f/4096.f);
        float var = fmaf(g_q2s[n*64 + tid], 1.f/4096.f, -m*m);
        msm[tid] = m;
        rsm[tid] = rsqrtf(var + EPSN);
    }
    __syncthreads();

    float r[64];
    float rnorm2 = 0.f;
    if (owner){
        #pragma unroll
        for (int c = 0; c < 64; c++){
            r[c] = fmaxf((encp[(size_t)c * 4096] - msm[c]) * rsm[c], 0.f);
            rnorm2 = fmaf(r[c], r[c], rnorm2);
        }
    }
    float lossacc = 0.f;

    const int arow = (l & 7) + ((l >> 3) & 1) * 8;
    const int akb  = ((l >> 4) & 1) * 16;
    const int t4   = l >> 3;
    const int browb = ((t4 >> 1) & 1) * 8 + (l & 7);
    const int bkb   = (t4 & 1) * 16;

    for (int st = 0; st < 6; st++){
        if (owner){
            #pragma unroll
            for (int j = 0; j < 32; j++){
                __nv_bfloat162 bv = __float22bfloat162_rn(make_float2(r[2*j], r[2*j+1]));
                uint32_t byte = (uint32_t)tid*128 + j*4;
                *(uint32_t*)(smc + R6_A + SWZ128(byte)) = *(uint32_t*)&bv;
            }
        }
        #pragma unroll
        for (int t = 0; t < 2; t++)
            norms[tid + t*256] = g_cbnorm[st*512 + tid + t*256];

        // fragment min state carried across chunks: idx = m*2 + half
        float M1[8], M2[8]; int I1[8];
        #pragma unroll
        for (int i = 0; i < 8; i++){ M1[i] = 3.4e38f; M2[i] = 3.4e38f; I1[i] = 0; }

        for (int cc = 0; cc < 2; cc++){
            __syncthreads();
            {
                const uint4* csrc = (const uint4*)(g_cb_bf16 + (size_t)st*32768 + cc*16384);
                #pragma unroll
                for (int t = 0; t < 8; t++){
                    int i = tid + t*256;
                    int code = i >> 3, c8 = i & 7;
                    uint32_t byte = (uint32_t)code*128 + c8*16;
                    *(uint4*)(smc + R6_CB + (byte ^ ((code & 7) << 4))) = csrc[i];
                }
            }
            __syncthreads();
            #pragma unroll
            for (int m = 0; m < 4; m++){
                uint32_t afr[4][4];
                #pragma unroll
                for (int k = 0; k < 4; k++){
                    uint32_t byte = (uint32_t)(m*16 + arow)*128 + (k*32 + akb);
                    ldsm_x4(afr[k], sb + R6_A + SWZ128(byte));
                }
                int row0 = m*16 + g;
                char* p0 = smc + R6_SC + (size_t)row0*1036;
                char* p1 = p0 + 8*1036;
                #pragma unroll
                for (int ch = 0; ch < 2; ch++){
                    int nbl = 32*w + 16*ch;
                    uint32_t bfr[4][4];
                    #pragma unroll
                    for (int k = 0; k < 4; k++){
                        uint32_t byte = (uint32_t)(nbl + browb)*128 + (k*32 + bkb);
                        ldsm_x4(bfr[k], sb + R6_CB + SWZ128(byte));
                    }
                    float clo[4] = {0.f,0.f,0.f,0.f};
                    float chi[4] = {0.f,0.f,0.f,0.f};
                    #pragma unroll
                    for (int k = 0; k < 4; k++){
                        mma16816(clo, afr[k], bfr[k][0], bfr[k][1]);
                        mma16816(chi, afr[k], bfr[k][2], bfr[k][3]);
                    }
                    int k0 = cc*256 + nbl + tig*2, k1 = k0 + 8;
                    float2 nm0 = *(float2*)(norms + k0);
                    float2 nm1 = *(float2*)(norms + k1);
                    float s00 = fmaf(-2.f, clo[0], nm0.x);
                    float s01 = fmaf(-2.f, clo[1], nm0.y);
                    float s10 = fmaf(-2.f, clo[2], nm0.x);
                    float s11 = fmaf(-2.f, clo[3], nm0.y);
                    float t00 = fmaf(-2.f, chi[0], nm1.x);
                    float t01 = fmaf(-2.f, chi[1], nm1.y);
                    float t10 = fmaf(-2.f, chi[2], nm1.x);
                    float t11 = fmaf(-2.f, chi[3], nm1.y);
                    UPD(M1[m*2],I1[m*2],M2[m*2],     s00, k0);
                    UPD(M1[m*2],I1[m*2],M2[m*2],     s01, k0+1);
                    UPD(M1[m*2],I1[m*2],M2[m*2],     t00, k1);
                    UPD(M1[m*2],I1[m*2],M2[m*2],     t01, k1+1);
                    UPD(M1[m*2+1],I1[m*2+1],M2[m*2+1], s10, k0);
                    UPD(M1[m*2+1],I1[m*2+1],M2[m*2+1], s11, k0+1);
                    UPD(M1[m*2+1],I1[m*2+1],M2[m*2+1], t10, k1);
                    UPD(M1[m*2+1],I1[m*2+1],M2[m*2+1], t11, k1+1);
                    *(__half2*)(p0 + k0*2) = __floats2half2_rn(s00, s01);
                    *(__half2*)(p1 + k0*2) = __floats2half2_rn(s10, s11);
                    *(__half2*)(p0 + k1*2) = __floats2half2_rn(t00, t01);
                    *(__half2*)(p1 + k1*2) = __floats2half2_rn(t10, t11);
                }
            }
        }
        // shfl reduce + minbuf write (once per stage)
        #pragma unroll
        for (int m = 0; m < 4; m++){
            float m1a = M1[m*2],   m2a = M2[m*2];   int i1a = I1[m*2];
            float m1b = M1[m*2+1], m2b = M2[m*2+1]; int i1b = I1[m*2+1];
            #pragma unroll
            for (int d = 1; d <= 2; d <<= 1){
                float om1 = __shfl_xor_sync(0xffffffffu, m1a, d);
                int   oi1 = __shfl_xor_sync(0xffffffffu, i1a, d);
                float om2 = __shfl_xor_sync(0xffffffffu, m2a, d);
                MERGE(m1a,i1a,m2a, om1,oi1,om2);
                om1 = __shfl_xor_sync(0xffffffffu, m1b, d);
                oi1 = __shfl_xor_sync(0xffffffffu, i1b, d);
                om2 = __shfl_xor_sync(0xffffffffu, m2b, d);
                MERGE(m1b,i1b,m2b, om1,oi1,om2);
            }
            if (tig == 0){
                int row0 = m*16 + g;
                char* e0 = smc + R6_MB + (size_t)(w*64 + row0)*12;
                char* e1 = smc + R6_MB + (size_t)(w*64 + row0 + 8)*12;
                ((float*)e0)[0] = m1a; ((float*)e0)[1] = m2a; ((int*)e0)[2] = i1a;
                ((float*)e1)[0] = m1b; ((float*)e1)[1] = m2b; ((int*)e1)[2] = i1b;
            }
        }
        __syncthreads();

        if (owner){
            float gm1 = 3.4e38f, gm2 = 3.4e38f; int gi1 = 0;
            #pragma unroll
            for (int e8 = 0; e8 < 8; e8++){
                const char* e = smc + R6_MB + (size_t)(e8*64 + tid)*12;
                float om1 = ((const float*)e)[0], om2 = ((const float*)e)[1];
                int   oi1 = ((const int*)e)[2];
                MERGE(gm1,gi1,gm2, om1,oi1,om2);
            }
            float srn  = sqrtf(rnorm2);
            float bmax = g_bmax[st];
            float margin = fmaf(0.0157f*srn, bmax,
                           fmaf(5e-4f, fmaf(2.f*srn, bmax, bmax*bmax), 1e-3f));
            int bestk = gi1;
            bool need = (gm2 - gm1) <= 2.f*margin;
            if (__any_sync(0xffffffffu, need)){
                if (need){
                    float thresh = gm1 + 2.f*margin;
                    const char* srow = smc + R6_SC + (size_t)tid*1036;
                    float bex = 3.4e38f; int bk = gi1;
                    for (int i = 0; i < 256; i++){
                        float2 s = __half22float2(*(const __half2*)(srow + i*4));
                        #pragma unroll
                        for (int h = 0; h < 2; h++){
                            float sv = h ? s.y : s.x;
                            if (sv <= thresh){
                                int k = 2*i + h;
                                const float4* ep = (const float4*)(cb + (size_t)st*32768 + (size_t)k*64);
                                float d0=0.f,d1=0.f,d2=0.f,d3=0.f;
                                #pragma unroll
                                for (int q = 0; q < 16; q++){
                                    float4 e = ep[q];
                                    d0 = fmaf(r[4*q+0], e.x, d0);
                                    d1 = fmaf(r[4*q+1], e.y, d1);
                                    d2 = fmaf(r[4*q+2], e.z, d2);
                                    d3 = fmaf(r[4*q+3], e.w, d3);
                                }
                                float sex = fmaf(-2.f, (d0+d1)+(d2+d3), g_cbnorm[st*512 + k]);
                                if (sex < bex){ bex = sex; bk = k; }
                            }
                        }
                    }
                    bestk = bk;
                }
            }
            const float4* ep = (const float4*)(cb + (size_t)st*32768 + (size_t)bestk*64);
            float rn = 0.f;
            #pragma unroll
            for (int q = 0; q < 16; q++){
                float4 e = ep[q];
                r[4*q+0] -= e.x; r[4*q+1] -= e.y; r[4*q+2] -= e.z; r[4*q+3] -= e.w;
                rn = fmaf(r[4*q+0], r[4*q+0], rn);
                rn = fmaf(r[4*q+1], r[4*q+1], rn);
                rn = fmaf(r[4*q+2], r[4*q+2], rn);
                rn = fmaf(r[4*q+3], r[4*q+3], rn);
            }
            rnorm2 = rn;
            lossacc += rn;
        }
        __syncthreads();
    }

    if (owner){
        lossacc = warpsum(lossacc);
        if (l == 0) red[w] = lossacc;
    }
    if (tid < 64){
        float m = g_m2s[n*64 + tid] * (1.f/4096.f);
        float var = fmaf(g_q2s[n*64 + tid], 1.f/4096.f, -m*m);
        msm[tid] = m;
        rsm[tid] = rsqrtf(var + EPSN);
    }
    __syncthreads();
    if (tid == 0){
        atomicAdd(&g_loss, (red[0] + red[1]) * (1.25f / 8388608.f));
    }
    if (owner){
        float* dp = g_dec_in + (size_t)n * 64 * 4096 + pix;
        #pragma unroll
        for (int c = 0; c < 64; c++){
            float xn = fmaxf((encp[(size_t)c * 4096] - msm[c]) * rsm[c], 0.f);
            dp[(size_t)c * 4096] = xn - r[c];
        }
    }
}

// ---------------- deconv1 (smem-tiled) ---------------------------------------
__global__ __launch_bounds__(512) void k_deconv1(const float* __restrict__ w,
                                                 const float* __restrict__ b){
    float* wsm  = dynsm;
    float* tile = dynsm + 16384;
    int tid = threadIdx.x;
    for (int i = tid; i < 16384; i += 512){
        int co = i >> 10, idx = i & 1023;
        wsm[idx*16 + co] = w[i];
    }
    int n     = blockIdx.x >> 4;
    int chunk = blockIdx.x & 15;
    int ihg0 = chunk*4 - 1;
    const float* din = g_dec_in + (size_t)n * 64 * 4096;
    for (int i = tid; i < 64*6*68; i += 512){
        int ci = i / 408, rem = i % 408;
        int rr = rem / 68, c = rem % 68;
        int ihg = ihg0 + rr, iwg = c - 1;
        float v = 0.f;
        if ((unsigned)ihg < 64u && (unsigned)iwg < 64u)
            v = din[ci*4096 + ihg*64 + iwg];
        tile[i] = v;
    }
    __syncthreads();

    int rowl = tid >> 6, colA = tid & 63;
    int oh = chunk*8 + rowl;
    ull accA[8], accB[8];
    #pragma unroll
    for (int j = 0; j < 8; j++){ accA[j] = pack2(b[2*j], b[2*j+1]); accB[j] = accA[j]; }
    int p = rowl & 1, q = colA & 1;
    int lih0 = ((rowl + p - 2) >> 1) + 1;
    int lih1 = lih0 + 1;
    int liwA0 = ((colA + q - 2) >> 1) + 1;
    int liwA1 = liwA0 + 1;
    const int i00 = p*4 + q, i01 = p*4 + q + 2, i10 = (p+2)*4 + q, i11 = (p+2)*4 + q + 2;
    for (int ci = 0; ci < 64; ci++){
        const float* tb = tile + ci*408;
        const float* r0 = tb + lih0*68;
        const float* r1 = tb + lih1*68;
        float vA00 = r0[liwA0], vA01 = r0[liwA1];
        float vA10 = r1[liwA0], vA11 = r1[liwA1];
        float vB00 = r0[liwA0+32], vB01 = r0[liwA1+32];
        float vB10 = r1[liwA0+32], vB11 = r1[liwA1+32];
        ull pA00 = pack2(vA00, vA00), pA01 = pack2(vA01, vA01);
        ull pA10 = pack2(vA10, vA10), pA11 = pack2(vA11, vA11);
        ull pB00 = pack2(vB00, vB00), pB01 = pack2(vB01, vB01);
        ull pB10 = pack2(vB10, vB10), pB11 = pack2(vB11, vB11);
        const ull* w00 = (const ull*)(wsm + (ci*16 + i00)*16);
        const ull* w01 = (const ull*)(wsm + (ci*16 + i01)*16);
        const ull* w10 = (const ull*)(wsm + (ci*16 + i10)*16);
        const ull* w11 = (const ull*)(wsm + (ci*16 + i11)*16);
        #pragma unroll
        for (int j = 0; j < 8; j++){
            ull a = w00[j], bb = w01[j], c = w10[j], d = w11[j];
            FMA2(accA[j], pA00, a); FMA2(accB[j], pB00, a);
            FMA2(accA[j], pA01, bb); FMA2(accB[j], pB01, bb);
            FMA2(accA[j], pA10, c); FMA2(accB[j], pB10, c);
            FMA2(accA[j], pA11, d); FMA2(accB[j], pB11, d);
        }
    }
    float* outp = g_d1 + (size_t)n * 16 * 16384 + oh*128 + colA;
    #pragma unroll
    for (int j = 0; j < 8; j++){
        float2 fA = unpack2(accA[j]), fB = unpack2(accB[j]);
        outp[(size_t)(2*j  ) * 16384]      = fA.x;
        outp[(size_t)(2*j+1) * 16384]      = fA.y;
        outp[(size_t)(2*j  ) * 16384 + 64] = fB.x;
        outp[(size_t)(2*j+1) * 16384 + 64] = fB.y;
    }
}

// ---------------- batchnorm stats --------------------------------------------
__global__ __launch_bounds__(256) void k_bnstats(){
    int c = blockIdx.x & 15, nn = blockIdx.x >> 4;
    const float4* sp = (const float4*)(g_d1 + (size_t)(nn*16 + c) * 16384);
    float s = 0.f, q = 0.f;
    for (int i = threadIdx.x; i < 4096; i += 256){
        float4 xv = sp[i];
        s += xv.x + xv.y + xv.z + xv.w;
        q = fmaf(xv.x, xv.x, fmaf(xv.y, xv.y, fmaf(xv.z, xv.z, fmaf(xv.w, xv.w, q))));
    }
    __shared__ float rsum[8], rsq[8];
    s = warpsum(s); q = warpsum(q);
    int wid = threadIdx.x >> 5, lane = threadIdx.x & 31;
    if (lane == 0){ rsum[wid] = s; rsq[wid] = q; }
    __syncthreads();
    if (threadIdx.x == 0){
        float S = 0.f, Q = 0.f;
        #pragma unroll
        for (int i = 0; i < 8; i++){ S += rsum[i]; Q += rsq[i]; }
        atomicAdd(&g_bn_s[c], S);
        atomicAdd(&g_bn_q[c], Q);
    }
}

// ---------------- deconv2 (smem-tiled) ---------------------------------------
__global__ __launch_bounds__(512) void k_deconv2(const float* __restrict__ w,
                                                 const float* __restrict__ b,
                                                 const float* __restrict__ gamma,
                                                 const float* __restrict__ beta,
                                                 float* __restrict__ out){
    __shared__ ull   wp[256];
    __shared__ float w2[256];
    __shared__ float Asm[16], Bsm[16];
    float* tile = dynsm;
    int tid = threadIdx.x;
    if (tid < 256){
        wp[tid] = pack2(w[tid], w[256 + tid]);
        w2[tid] = w[512 + tid];
    }
    if (tid < 16){
        const float Nc = 32.f * 128.f * 128.f;
        float m = g_bn_s[tid] / Nc;
        float var = g_bn_q[tid] / Nc - m*m;
        float A = rsqrtf(var + EPSN) * gamma[tid];
        Asm[tid] = A;
        Bsm[tid] = fmaf(-m, A, beta[tid]);
    }
    __syncthreads();

    int n     = blockIdx.x >> 5;
    int chunk = blockIdx.x & 31;
    int ihg0 = chunk*4 - 1;
    const float* din = g_d1 + (size_t)n * 16 * 16384;
    for (int i = tid; i < 16*6*132; i += 512){
        int ci = i / 792, rem = i % 792;
        int rr = rem / 132, c = rem % 132;
        int ihg = ihg0 + rr, iwg = c - 1;
        float v = 0.f;
        if ((unsigned)ihg < 128u && (unsigned)iwg < 128u)
            v = fmaf(din[ci*16384 + ihg*128 + iwg], Asm[ci], Bsm[ci]);
        tile[i] = v;
    }
    __syncthreads();

    int rowl = tid >> 6, colA = tid & 63;
    int oh = chunk*8 + rowl;
    ull acc01[4];
    float acc2[4];
    #pragma unroll
    for (int px = 0; px < 4; px++){ acc01[px] = pack2(b[0], b[1]); acc2[px] = b[2]; }
    int p = rowl & 1, q = colA & 1;
    int lih0 = ((rowl + p - 2) >> 1) + 1;
    int lih1 = lih0 + 1;
    int liw0 = ((colA + q - 2) >> 1) + 1;
    const int i00 = p*4 + q, i01 = p*4 + q + 2, i10 = (p+2)*4 + q, i11 = (p+2)*4 + q + 2;
    for (int ci = 0; ci < 16; ci++){
        const float* tb = tile + ci*792;
        const float* r0 = tb + lih0*132;
        const float* r1 = tb + lih1*132;
        ull wa = wp[ci*16 + i00], wb = wp[ci*16 + i01];
        ull wc = wp[ci*16 + i10], wd = wp[ci*16 + i11];
        float s2a = w2[ci*16 + i00], s2b = w2[ci*16 + i01];
        float s2c = w2[ci*16 + i10], s2d = w2[ci*16 + i11];
        #pragma unroll
        for (int px = 0; px < 4; px++){
            int o = liw0 + px*32;
            float v00 = r0[o], v01 = r0[o+1];
            float v10 = r1[o], v11 = r1[o+1];
            FMA2(acc01[px], pack2(v00,v00), wa);
            FMA2(acc01[px], pack2(v01,v01), wb);
            FMA2(acc01[px], pack2(v10,v10), wc);
            FMA2(acc01[px], pack2(v11,v11), wd);
            acc2[px] = fmaf(v00, s2a, fmaf(v01, s2b, fmaf(v10, s2c, fmaf(v11, s2d, acc2[px]))));
        }
    }
    float* outp = out + (size_t)n * 3 * 65536 + oh*256 + colA;
    #pragma unroll
    for (int px = 0; px < 4; px++){
        float2 f01 = unpack2(acc01[px]);
        outp[px*64]          = f01.x;
        outp[px*64 + 65536]  = f01.y;
        outp[px*64 + 131072] = acc2[px];
    }
}

__global__ void k_write_loss(float* __restrict__ out, int idx){
    if (threadIdx.x == 0) out[idx] = g_loss;
}

// ---------------- launch -----------------------------------------------------
extern "C" void kernel_launch(void* const* d_in, const int* in_sizes, int n_in,
                              void* d_out, int out_size){
    const float* x     = (const float*)d_in[0];
    const float* ew1   = (const float*)d_in[1];
    const float* eb1   = (const float*)d_in[2];
    const float* ew2   = (const float*)d_in[3];
    const float* eb2   = (const float*)d_in[4];
    const float* cb    = (const float*)d_in[5];
    const float* dw1   = (const float*)d_in[6];
    const float* db1   = (const float*)d_in[7];
    const float* gamma = (const float*)d_in[8];
    const float* beta  = (const float*)d_in[9];
    const float* dw2   = (const float*)d_in[10];
    const float* db2   = (const float*)d_in[11];
    float* out = (float*)d_out;

    const int conv2_smem   = (16384 + 16*18*132) * 4;
    const int deconv1_smem = (16384 + 64*6*68) * 4;
    const int deconv2_smem = (16*6*132) * 4;

    cudaFuncSetAttribute(k_conv2s,  cudaFuncAttributeMaxDynamicSharedMemorySize, conv2_smem);
    cudaFuncSetAttribute(k_rvq6,    cudaFuncAttributeMaxDynamicSharedMemorySize, RVQ6_SMEM);
    cudaFuncSetAttribute(k_deconv1, cudaFuncAttributeMaxDynamicSharedMemorySize, deconv1_smem);
    cudaFuncSetAttribute(k_deconv2, cudaFuncAttributeMaxDynamicSharedMemorySize, deconv2_smem);

    k_conv1x<<<512, 512>>>(x, ew1, eb1, cb);           // 1
    k_statsnorm<<<512, 512>>>(0);                      // 2
    k_conv2s<<<256, 512, conv2_smem>>>(ew2, eb2);      // 3
    k_rvq6<<<2048, 256, RVQ6_SMEM>>>(cb);              // 4  <- ncu slot
    k_deconv1<<<512, 512, deconv1_smem>>>(dw1, db1);   // 5
    k_bnstats<<<512, 256>>>();                         // 6
    k_deconv2<<<1024, 512, deconv2_smem>>>(dw2, db2, gamma, beta, out); // 7
    k_write_loss<<<1, 32>>>(out, out_size - 1);        // 8
}

// round 15
// speedup vs baseline: 1.5827x; 1.5827x over previous
#include <cuda_runtime.h>
#include <cuda_bf16.h>
#include <cuda_fp16.h>
#include <cstdint>

#define EPSN 1e-5f

__device__ float g_h1[32*16*128*128];
__device__ float g_enc[32*64*64*64];
__device__ float g_dec_in[32*64*64*64];
__device__ float g_d1[32*16*128*128];
__device__ float g_bn_s[16], g_bn_q[16];
__device__ float g_m2s[2048], g_q2s[2048];
__device__ float g_loss;
__device__ __nv_bfloat16 g_cb_bf16[6*512*64];
__device__ float g_cbnorm[6*512];
__device__ float g_bmax[6];

extern __shared__ float dynsm[];

typedef unsigned long long ull;

#define FMA2(acc, a, b_) asm("fma.rn.f32x2 %0, %1, %2, %3;" : "=l"(acc) : "l"(a), "l"(b_), "l"(acc))

__device__ __forceinline__ float2 unpack2(ull p){
    float2 f; asm("mov.b64 {%0,%1}, %2;" : "=f"(f.x), "=f"(f.y) : "l"(p)); return f;
}
__device__ __forceinline__ ull pack2(float lo, float hi){
    ull p; asm("mov.b64 %0, {%1,%2};" : "=l"(p) : "f"(lo), "f"(hi)); return p;
}
__device__ __forceinline__ float warpsum(float v){
    #pragma unroll
    for (int o = 16; o; o >>= 1) v += __shfl_down_sync(0xffffffffu, v, o);
    return v;
}
__device__ __forceinline__ uint32_t smem_u32(const void* p){
    uint32_t a;
    asm("{ .reg .u64 t; cvta.to.shared.u64 t, %1; cvt.u32.u64 %0, t; }" : "=r"(a) : "l"(p));
    return a;
}

#define SWZ128(b) ((b) ^ (((b) >> 3) & 0x70))

__device__ __forceinline__ void mma16816(float c[4], const uint32_t a[4],
                                         uint32_t b0, uint32_t b1){
    asm volatile(
        "mma.sync.aligned.m16n8k16.row.col.f32.bf16.bf16.f32 "
        "{%0,%1,%2,%3}, {%4,%5,%6,%7}, {%8,%9}, {%0,%1,%2,%3};"
        : "+f"(c[0]), "+f"(c[1]), "+f"(c[2]), "+f"(c[3])
        : "r"(a[0]), "r"(a[1]), "r"(a[2]), "r"(a[3]), "r"(b0), "r"(b1));
}
__device__ __forceinline__ void ldsm_x4(uint32_t r[4], uint32_t addr){
    asm volatile("ldmatrix.sync.aligned.m8n8.x4.shared.b16 {%0,%1,%2,%3}, [%4];"
        : "=r"(r[0]), "=r"(r[1]), "=r"(r[2]), "=r"(r[3]) : "r"(addr));
}

#define UPD(m1,i1,m2,s,k) do{ \
    if ((s) < (m1)){ (m2)=(m1); (m1)=(s); (i1)=(k); } \
    else if ((s) < (m2)){ (m2)=(s); } }while(0)

#define MERGE(m1,i1,m2,om1,oi1,om2) do{ \
    if ((om1) < (m1)){ (m2) = fminf((m1), (om2)); (m1)=(om1); (i1)=(oi1); } \
    else if ((om1) < (m2)){ (m2)=(om1); } }while(0)

// ---------------- conv1 + cbprep + zeroing -----------------------------------
__global__ __launch_bounds__(512) void k_conv1x(const float* __restrict__ x,
                                                const float* __restrict__ w,
                                                const float* __restrict__ b,
                                                const float* __restrict__ cb){
    __shared__ float wsm[48][16];
    __shared__ float mx[16];
    int tid = threadIdx.x;
    for (int i = tid; i < 768; i += 512){
        int co = i / 48, idx = i % 48;
        wsm[idx][co] = w[i];
    }
    __syncthreads();
    int n     = blockIdx.x >> 4;
    int chunk = blockIdx.x & 15;
    int row = tid >> 6, col = tid & 63;
    int oh = chunk*8 + row;
    ull accA[8], accB[8];
    #pragma unroll
    for (int j = 0; j < 8; j++){ accA[j] = pack2(b[2*j], b[2*j+1]); accB[j] = accA[j]; }
    const float* xn = x + (size_t)n * 3 * 65536;
    for (int ci = 0; ci < 3; ci++){
        #pragma unroll
        for (int kh = 0; kh < 4; kh++){
            int ih = 2*oh + kh - 1;
            if ((unsigned)ih >= 256u) continue;
            const float* rowp = xn + (ci*256 + ih)*256;
            #pragma unroll
            for (int kw = 0; kw < 4; kw++){
                int iwA = 2*col + kw - 1;
                int iwB = iwA + 128;
                float vA = ((unsigned)iwA < 256u) ? rowp[iwA] : 0.f;
                float vB = ((unsigned)iwB < 256u) ? rowp[iwB] : 0.f;
                ull vA2 = pack2(vA, vA), vB2 = pack2(vB, vB);
                const ull* wr = (const ull*)wsm[ci*16 + kh*4 + kw];
                #pragma unroll
                for (int j = 0; j < 8; j++){
                    FMA2(accA[j], vA2, wr[j]);
                    FMA2(accB[j], vB2, wr[j]);
                }
            }
        }
    }
    float* outp = g_h1 + (size_t)n * 16 * 16384 + oh*128 + col;
    #pragma unroll
    for (int j = 0; j < 8; j++){
        float2 fA = unpack2(accA[j]), fB = unpack2(accB[j]);
        outp[(size_t)(2*j  ) * 16384]      = fA.x;
        outp[(size_t)(2*j+1) * 16384]      = fA.y;
        outp[(size_t)(2*j  ) * 16384 + 64] = fB.x;
        outp[(size_t)(2*j+1) * 16384 + 64] = fB.y;
    }
    if (blockIdx.x < 6){
        int st = blockIdx.x, k = tid;
        const float* row2 = cb + (size_t)(st*512 + k) * 64;
        float s = 0.f;
        __nv_bfloat162* dst = (__nv_bfloat162*)g_cb_bf16 + (size_t)(st*512 + k) * 32;
        #pragma unroll
        for (int j = 0; j < 32; j++){
            float a = row2[2*j], b2 = row2[2*j+1];
            s = fmaf(a, a, fmaf(b2, b2, s));
            dst[j] = __float22bfloat162_rn(make_float2(a, b2));
        }
        g_cbnorm[st*512 + k] = s;
        float m = s;
        #pragma unroll
        for (int o = 16; o; o >>= 1) m = fmaxf(m, __shfl_down_sync(0xffffffffu, m, o));
        int wid = k >> 5;
        if ((k & 31) == 0) mx[wid] = m;
        __syncthreads();
        if (k == 0){
            float M = 0.f;
            #pragma unroll
            for (int i = 0; i < 16; i++) M = fmaxf(M, mx[i]);
            g_bmax[st] = sqrtf(M);
        }
    } else if (blockIdx.x < 14){
        int i = (blockIdx.x - 6) * 512 + tid;
        if (i < 2048) g_m2s[i] = 0.f;
        else          g_q2s[i - 2048] = 0.f;
    } else if (blockIdx.x == 14){
        if (tid == 0) g_loss = 0.f;
        if (tid < 16){ g_bn_s[tid] = 0.f; g_bn_q[tid] = 0.f; }
    }
}

// ---------------- fused per-plane stats + normalize + relu (g_h1) -----------
__global__ __launch_bounds__(512) void k_statsnorm(int mode){
    int p = blockIdx.x;
    float* sp; int plane;
    if (mode == 0){ sp = g_h1 + (size_t)p*16384; plane = 16384; }
    else          { sp = g_enc + (size_t)p*4096; plane = 4096; }
    float s = 0.f, q = 0.f;
    float4* sp4 = (float4*)sp;
    for (int i = threadIdx.x; i < plane/4; i += 512){
        float4 xv = sp4[i];
        s += xv.x + xv.y + xv.z + xv.w;
        q = fmaf(xv.x, xv.x, fmaf(xv.y, xv.y, fmaf(xv.z, xv.z, fmaf(xv.w, xv.w, q))));
    }
    __shared__ float rsum[16], rsq[16];
    __shared__ float sm_m, sm_r;
    s = warpsum(s); q = warpsum(q);
    int wid = threadIdx.x >> 5, lane = threadIdx.x & 31;
    if (lane == 0){ rsum[wid] = s; rsq[wid] = q; }
    __syncthreads();
    if (threadIdx.x == 0){
        float S = 0.f, Q = 0.f;
        #pragma unroll
        for (int i = 0; i < 16; i++){ S += rsum[i]; Q += rsq[i]; }
        float inv = 1.f / (float)plane;
        float mm = S * inv;
        sm_m = mm;
        sm_r = rsqrtf(Q * inv - mm*mm + EPSN);
    }
    __syncthreads();
    float m = sm_m, r = sm_r;
    for (int i = threadIdx.x; i < plane/4; i += 512){
        float4 xv = sp4[i];
        xv.x = fmaxf((xv.x - m) * r, 0.f);
        xv.y = fmaxf((xv.y - m) * r, 0.f);
        xv.z = fmaxf((xv.z - m) * r, 0.f);
        xv.w = fmaxf((xv.w - m) * r, 0.f);
        sp4[i] = xv;
    }
}

// ---------------- conv2 + fused enc stats ------------------------------------
__global__ __launch_bounds__(512) void k_conv2s(const float* __restrict__ w,
                                                const float* __restrict__ b){
    float* wsm = dynsm;
    float* tile = dynsm + 16384;
    int tid = threadIdx.x;
    for (int i = tid; i < 16384; i += 512){
        int co = i >> 8, idx = i & 255;
        wsm[idx*64 + co] = w[i];
    }
    int n   = blockIdx.x >> 3;
    int oh0 = (blockIdx.x & 7) << 3;
    int ihg0 = 2*oh0 - 1;
    const float* hn = g_h1 + (size_t)n * 16 * 16384;
    for (int i = tid; i < 16*18*132; i += 512){
        int ci = i / 2376, rem = i % 2376;
        int r = rem / 132, c = rem % 132;
        int ihg = ihg0 + r, iwg = c - 1;
        float v = 0.f;
        if ((unsigned)ihg < 128u && (unsigned)iwg < 128u)
            v = hn[(ci*128 + ihg)*128 + iwg];
        tile[i] = v;
    }
    __syncthreads();
    int rowl = tid >> 6, coq = (tid >> 4) & 3, colb = tid & 15;
    ull acc[4][8];
    #pragma unroll
    for (int px = 0; px < 4; px++)
        #pragma unroll
        for (int j = 0; j < 8; j++)
            acc[px][j] = pack2(b[16*coq + 2*j], b[16*coq + 2*j + 1]);
    for (int ci = 0; ci < 16; ci++){
        const float* tci = tile + ci*2376;
        #pragma unroll
        for (int kh = 0; kh < 4; kh++){
            const float* trow = tci + (2*rowl + kh)*132 + 2*colb;
            #pragma unroll
            for (int kw = 0; kw < 4; kw++){
                float v0 = trow[kw];
                float v1 = trow[kw + 32];
                float v2 = trow[kw + 64];
                float v3 = trow[kw + 96];
                ull p0 = pack2(v0, v0), p1 = pack2(v1, v1);
                ull p2 = pack2(v2, v2), p3 = pack2(v3, v3);
                const ull* wr = (const ull*)(wsm + (ci*16 + kh*4 + kw)*64 + 16*coq);
                #pragma unroll
                for (int j = 0; j < 8; j++){
                    ull ww = wr[j];
                    FMA2(acc[0][j], p0, ww);
                    FMA2(acc[1][j], p1, ww);
                    FMA2(acc[2][j], p2, ww);
                    FMA2(acc[3][j], p3, ww);
                }
            }
        }
    }
    int oh = oh0 + rowl;
    float* outp = g_enc + (size_t)n * 64 * 4096 + (size_t)(16*coq) * 4096 + oh*64 + colb;
    #pragma unroll
    for (int px = 0; px < 4; px++){
        #pragma unroll
        for (int j = 0; j < 8; j++){
            float2 f = unpack2(acc[px][j]);
            outp[(size_t)(2*j  ) * 4096 + px*16] = f.x;
            outp[(size_t)(2*j+1) * 4096 + px*16] = f.y;
        }
    }
    #pragma unroll
    for (int j = 0; j < 8; j++){
        float s0 = 0.f, s1 = 0.f, q0 = 0.f, q1 = 0.f;
        #pragma unroll
        for (int px = 0; px < 4; px++){
            float2 f = unpack2(acc[px][j]);
            s0 += f.x; s1 += f.y;
            q0 = fmaf(f.x, f.x, q0);
            q1 = fmaf(f.y, f.y, q1);
        }
        #pragma unroll
        for (int o = 8; o; o >>= 1){
            s0 += __shfl_down_sync(0xffffffffu, s0, o, 16);
            s1 += __shfl_down_sync(0xffffffffu, s1, o, 16);
            q0 += __shfl_down_sync(0xffffffffu, q0, o, 16);
            q1 += __shfl_down_sync(0xffffffffu, q1, o, 16);
        }
        if ((tid & 15) == 0){
            int co = 16*coq + 2*j;
            atomicAdd(&g_m2s[n*64 + co],     s0);
            atomicAdd(&g_m2s[n*64 + co + 1], s1);
            atomicAdd(&g_q2s[n*64 + co],     q0);
            atomicAdd(&g_q2s[n*64 + co + 1], q1);
        }
    }
}

// ---------------- RVQ v5b (R13-proven): 128 thr, 2 blocks/SM -----------------
#define R5_CB   0        // 32768
#define R5_A    32768    // 8192
#define R5_NRM  40960    // 2048
#define R5_MB   43008    // 6144 : minbuf (stage loop) / msm+rsm (pro/epilogue)
#define R5_SC   49152    // 66304
#define R5_RED  115456   // 64
#define RVQ5_SMEM 115520

__global__ __launch_bounds__(128, 2) void k_rvq5(const float* __restrict__ cb){
    char* smc = (char*)dynsm;
    float* norms = (float*)(smc + R5_NRM);
    float* msm   = (float*)(smc + R5_MB);
    float* rsm   = (float*)(smc + R5_MB + 256);
    float* red   = (float*)(smc + R5_RED);
    uint32_t sb = smem_u32(smc);
    int tid = threadIdx.x;
    int w = tid >> 5, l = tid & 31;
    int g = l >> 2, tig = l & 3;
    bool owner = tid < 64;

    int n   = blockIdx.x >> 6;
    int pix = ((blockIdx.x & 63) << 6) + (tid & 63);
    const float* encp = g_enc + (size_t)n * 64 * 4096 + pix;

    if (tid < 64){
        float m = g_m2s[n*64 + tid] * (1.f/4096.f);
        float var = fmaf(g_q2s[n*64 + tid], 1.f/4096.f, -m*m);
        msm[tid] = m;
        rsm[tid] = rsqrtf(var + EPSN);
    }
    __syncthreads();

    float r[64];
    float rnorm2 = 0.f;
    if (owner){
        #pragma unroll
        for (int c = 0; c < 64; c++){
            r[c] = fmaxf((encp[(size_t)c * 4096] - msm[c]) * rsm[c], 0.f);
            rnorm2 = fmaf(r[c], r[c], rnorm2);
        }
    }
    float lossacc = 0.f;

    const int arow = (l & 7) + ((l >> 3) & 1) * 8;
    const int akb  = ((l >> 4) & 1) * 16;
    const int t4   = l >> 3;
    const int browb = ((t4 >> 1) & 1) * 8 + (l & 7);
    const int bkb   = (t4 & 1) * 16;

    for (int st = 0; st < 6; st++){
        if (owner){
            #pragma unroll
            for (int j = 0; j < 32; j++){
                __nv_bfloat162 bv = __float22bfloat162_rn(make_float2(r[2*j], r[2*j+1]));
                uint32_t byte = (uint32_t)tid*128 + j*4;
                *(uint32_t*)(smc + R5_A + SWZ128(byte)) = *(uint32_t*)&bv;
            }
        }
        #pragma unroll
        for (int t = 0; t < 4; t++)
            norms[tid + t*128] = g_cbnorm[st*512 + tid + t*128];

        for (int cc = 0; cc < 2; cc++){
            __syncthreads();
            {
                const uint4* csrc = (const uint4*)(g_cb_bf16 + (size_t)st*32768 + cc*16384);
                #pragma unroll
                for (int t = 0; t < 16; t++){
                    int i = tid + t*128;
                    int code = i >> 3, c8 = i & 7;
                    uint32_t byte = (uint32_t)code*128 + c8*16;
                    *(uint4*)(smc + R5_CB + (byte ^ ((code & 7) << 4))) = csrc[i];
                }
            }
            __syncthreads();
            for (int m = 0; m < 4; m++){
                uint32_t afr[4][4];
                #pragma unroll
                for (int k = 0; k < 4; k++){
                    uint32_t byte = (uint32_t)(m*16 + arow)*128 + (k*32 + akb);
                    ldsm_x4(afr[k], sb + R5_A + SWZ128(byte));
                }
                int row0 = m*16 + g;
                char* p0 = smc + R5_SC + (size_t)row0*1036;
                char* p1 = p0 + 8*1036;
                float m1a = 3.4e38f, m2a = 3.4e38f; int i1a = 0;
                float m1b = 3.4e38f, m2b = 3.4e38f; int i1b = 0;
                #pragma unroll
                for (int ch = 0; ch < 4; ch++){
                    int nbl = 64*w + 16*ch;
                    uint32_t bfr[4][4];
                    #pragma unroll
                    for (int k = 0; k < 4; k++){
                        uint32_t byte = (uint32_t)(nbl + browb)*128 + (k*32 + bkb);
                        ldsm_x4(bfr[k], sb + R5_CB + SWZ128(byte));
                    }
                    float clo[4] = {0.f,0.f,0.f,0.f};
                    float chi[4] = {0.f,0.f,0.f,0.f};
                    #pragma unroll
                    for (int k = 0; k < 4; k++){
                        mma16816(clo, afr[k], bfr[k][0], bfr[k][1]);
                        mma16816(chi, afr[k], bfr[k][2], bfr[k][3]);
                    }
                    int k0 = cc*256 + nbl + tig*2, k1 = k0 + 8;
                    float2 nm0 = *(float2*)(norms + k0);
                    float2 nm1 = *(float2*)(norms + k1);
                    float s00 = fmaf(-2.f, clo[0], nm0.x);
                    float s01 = fmaf(-2.f, clo[1], nm0.y);
                    float s10 = fmaf(-2.f, clo[2], nm0.x);
                    float s11 = fmaf(-2.f, clo[3], nm0.y);
                    float t00 = fmaf(-2.f, chi[0], nm1.x);
                    float t01 = fmaf(-2.f, chi[1], nm1.y);
                    float t10 = fmaf(-2.f, chi[2], nm1.x);
                    float t11 = fmaf(-2.f, chi[3], nm1.y);
                    UPD(m1a,i1a,m2a, s00, k0);  UPD(m1a,i1a,m2a, s01, k0+1);
                    UPD(m1a,i1a,m2a, t00, k1);  UPD(m1a,i1a,m2a, t01, k1+1);
                    UPD(m1b,i1b,m2b, s10, k0);  UPD(m1b,i1b,m2b, s11, k0+1);
                    UPD(m1b,i1b,m2b, t10, k1);  UPD(m1b,i1b,m2b, t11, k1+1);
                    *(__half2*)(p0 + k0*2) = __floats2half2_rn(s00, s01);
                    *(__half2*)(p1 + k0*2) = __floats2half2_rn(s10, s11);
                    *(__half2*)(p0 + k1*2) = __floats2half2_rn(t00, t01);
                    *(__half2*)(p1 + k1*2) = __floats2half2_rn(t10, t11);
                }
                #pragma unroll
                for (int d = 1; d <= 2; d <<= 1){
                    float om1 = __shfl_xor_sync(0xffffffffu, m1a, d);
                    int   oi1 = __shfl_xor_sync(0xffffffffu, i1a, d);
                    float om2 = __shfl_xor_sync(0xffffffffu, m2a, d);
                    MERGE(m1a,i1a,m2a, om1,oi1,om2);
                    om1 = __shfl_xor_sync(0xffffffffu, m1b, d);
                    oi1 = __shfl_xor_sync(0xffffffffu, i1b, d);
                    om2 = __shfl_xor_sync(0xffffffffu, m2b, d);
                    MERGE(m1b,i1b,m2b, om1,oi1,om2);
                }
                if (tig == 0){
                    char* e0 = smc + R5_MB + (size_t)((cc*4 + w)*64 + row0)*12;
                    char* e1 = smc + R5_MB + (size_t)((cc*4 + w)*64 + row0 + 8)*12;
                    ((float*)e0)[0] = m1a; ((float*)e0)[1] = m2a; ((int*)e0)[2] = i1a;
                    ((float*)e1)[0] = m1b; ((float*)e1)[1] = m2b; ((int*)e1)[2] = i1b;
                }
            }
        }
        __syncthreads();

        int bestk = 0;
        if (owner){
            float gm1 = 3.4e38f, gm2 = 3.4e38f; int gi1 = 0;
            #pragma unroll
            for (int e8 = 0; e8 < 8; e8++){
                const char* e = smc + R5_MB + (size_t)(e8*64 + tid)*12;
                float om1 = ((const float*)e)[0], om2 = ((const float*)e)[1];
                int   oi1 = ((const int*)e)[2];
                MERGE(gm1,gi1,gm2, om1,oi1,om2);
            }
            float srn  = sqrtf(rnorm2);
            float bmax = g_bmax[st];
            float margin = fmaf(0.0157f*srn, bmax,
                           fmaf(5e-4f, fmaf(2.f*srn, bmax, bmax*bmax), 1e-3f));
            bestk = gi1;
            bool need = (gm2 - gm1) <= 2.f*margin;
            if (__any_sync(0xffffffffu, need)){
                if (need){
                    float thresh = gm1 + 2.f*margin;
                    const char* srow = smc + R5_SC + (size_t)tid*1036;
                    float bex = 3.4e38f; int bk = gi1;
                    for (int i = 0; i < 256; i++){
                        float2 s = __half22float2(*(const __half2*)(srow + i*4));
                        #pragma unroll
                        for (int h = 0; h < 2; h++){
                            float sv = h ? s.y : s.x;
                            if (sv <= thresh){
                                int k = 2*i + h;
                                const float4* ep = (const float4*)(cb + (size_t)st*32768 + (size_t)k*64);
                                float d0=0.f,d1=0.f,d2=0.f,d3=0.f;
                                #pragma unroll
                                for (int q = 0; q < 16; q++){
                                    float4 e = ep[q];
                                    d0 = fmaf(r[4*q+0], e.x, d0);
                                    d1 = fmaf(r[4*q+1], e.y, d1);
                                    d2 = fmaf(r[4*q+2], e.z, d2);
                                    d3 = fmaf(r[4*q+3], e.w, d3);
                                }
                                float sex = fmaf(-2.f, (d0+d1)+(d2+d3), g_cbnorm[st*512 + k]);
                                if (sex < bex){ bex = sex; bk = k; }
                            }
                        }
                    }
                    bestk = bk;
                }
            }
            const float4* ep = (const float4*)(cb + (size_t)st*32768 + (size_t)bestk*64);
            float rn = 0.f;
            #pragma unroll
            for (int q = 0; q < 16; q++){
                float4 e = ep[q];
                r[4*q+0] -= e.x; r[4*q+1] -= e.y; r[4*q+2] -= e.z; r[4*q+3] -= e.w;
                rn = fmaf(r[4*q+0], r[4*q+0], rn);
                rn = fmaf(r[4*q+1], r[4*q+1], rn);
                rn = fmaf(r[4*q+2], r[4*q+2], rn);
                rn = fmaf(r[4*q+3], r[4*q+3], rn);
            }
            rnorm2 = rn;
            lossacc += rn;
        }
        __syncthreads();
    }

    if (owner){
        lossacc = warpsum(lossacc);
        if (l == 0) red[w] = lossacc;
    }
    if (tid < 64){
        float m = g_m2s[n*64 + tid] * (1.f/4096.f);
        float var = fmaf(g_q2s[n*64 + tid], 1.f/4096.f, -m*m);
        msm[tid] = m;
        rsm[tid] = rsqrtf(var + EPSN);
    }
    __syncthreads();
    if (tid == 0){
        atomicAdd(&g_loss, (red[0] + red[1]) * (1.25f / 8388608.f));
    }
    if (owner){
        float* dp = g_dec_in + (size_t)n * 64 * 4096 + pix;
        #pragma unroll
        for (int c = 0; c < 64; c++){
            float xn = fmaxf((encp[(size_t)c * 4096] - msm[c]) * rsm[c], 0.f);
            dp[(size_t)c * 4096] = xn - r[c];
        }
    }
}

// ---------------- deconv1 (smem-tiled) ---------------------------------------
__global__ __launch_bounds__(512) void k_deconv1(const float* __restrict__ w,
                                                 const float* __restrict__ b){
    float* wsm  = dynsm;
    float* tile = dynsm + 16384;
    int tid = threadIdx.x;
    for (int i = tid; i < 16384; i += 512){
        int co = i >> 10, idx = i & 1023;
        wsm[idx*16 + co] = w[i];
    }
    int n     = blockIdx.x >> 4;
    int chunk = blockIdx.x & 15;
    int ihg0 = chunk*4 - 1;
    const float* din = g_dec_in + (size_t)n * 64 * 4096;
    for (int i = tid; i < 64*6*68; i += 512){
        int ci = i / 408, rem = i % 408;
        int rr = rem / 68, c = rem % 68;
        int ihg = ihg0 + rr, iwg = c - 1;
        float v = 0.f;
        if ((unsigned)ihg < 64u && (unsigned)iwg < 64u)
            v = din[ci*4096 + ihg*64 + iwg];
        tile[i] = v;
    }
    __syncthreads();

    int rowl = tid >> 6, colA = tid & 63;
    int oh = chunk*8 + rowl;
    ull accA[8], accB[8];
    #pragma unroll
    for (int j = 0; j < 8; j++){ accA[j] = pack2(b[2*j], b[2*j+1]); accB[j] = accA[j]; }
    int p = rowl & 1, q = colA & 1;
    int lih0 = ((rowl + p - 2) >> 1) + 1;
    int lih1 = lih0 + 1;
    int liwA0 = ((colA + q - 2) >> 1) + 1;
    int liwA1 = liwA0 + 1;
    const int i00 = p*4 + q, i01 = p*4 + q + 2, i10 = (p+2)*4 + q, i11 = (p+2)*4 + q + 2;
    for (int ci = 0; ci < 64; ci++){
        const float* tb = tile + ci*408;
        const float* r0 = tb + lih0*68;
        const float* r1 = tb + lih1*68;
        float vA00 = r0[liwA0], vA01 = r0[liwA1];
        float vA10 = r1[liwA0], vA11 = r1[liwA1];
        float vB00 = r0[liwA0+32], vB01 = r0[liwA1+32];
        float vB10 = r1[liwA0+32], vB11 = r1[liwA1+32];
        ull pA00 = pack2(vA00, vA00), pA01 = pack2(vA01, vA01);
        ull pA10 = pack2(vA10, vA10), pA11 = pack2(vA11, vA11);
        ull pB00 = pack2(vB00, vB00), pB01 = pack2(vB01, vB01);
        ull pB10 = pack2(vB10, vB10), pB11 = pack2(vB11, vB11);
        const ull* w00 = (const ull*)(wsm + (ci*16 + i00)*16);
        const ull* w01 = (const ull*)(wsm + (ci*16 + i01)*16);
        const ull* w10 = (const ull*)(wsm + (ci*16 + i10)*16);
        const ull* w11 = (const ull*)(wsm + (ci*16 + i11)*16);
        #pragma unroll
        for (int j = 0; j < 8; j++){
            ull a = w00[j], bb = w01[j], c = w10[j], d = w11[j];
            FMA2(accA[j], pA00, a); FMA2(accB[j], pB00, a);
            FMA2(accA[j], pA01, bb); FMA2(accB[j], pB01, bb);
            FMA2(accA[j], pA10, c); FMA2(accB[j], pB10, c);
            FMA2(accA[j], pA11, d); FMA2(accB[j], pB11, d);
        }
    }
    float* outp = g_d1 + (size_t)n * 16 * 16384 + oh*128 + colA;
    #pragma unroll
    for (int j = 0; j < 8; j++){
        float2 fA = unpack2(accA[j]), fB = unpack2(accB[j]);
        outp[(size_t)(2*j  ) * 16384]      = fA.x;
        outp[(size_t)(2*j+1) * 16384]      = fA.y;
        outp[(size_t)(2*j  ) * 16384 + 64] = fB.x;
        outp[(size_t)(2*j+1) * 16384 + 64] = fB.y;
    }
}

// ---------------- batchnorm stats --------------------------------------------
__global__ __launch_bounds__(256) void k_bnstats(){
    int c = blockIdx.x & 15, nn = blockIdx.x >> 4;
    const float4* sp = (const float4*)(g_d1 + (size_t)(nn*16 + c) * 16384);
    float s = 0.f, q = 0.f;
    for (int i = threadIdx.x; i < 4096; i += 256){
        float4 xv = sp[i];
        s += xv.x + xv.y + xv.z + xv.w;
        q = fmaf(xv.x, xv.x, fmaf(xv.y, xv.y, fmaf(xv.z, xv.z, fmaf(xv.w, xv.w, q))));
    }
    __shared__ float rsum[8], rsq[8];
    s = warpsum(s); q = warpsum(q);
    int wid = threadIdx.x >> 5, lane = threadIdx.x & 31;
    if (lane == 0){ rsum[wid] = s; rsq[wid] = q; }
    __syncthreads();
    if (threadIdx.x == 0){
        float S = 0.f, Q = 0.f;
        #pragma unroll
        for (int i = 0; i < 8; i++){ S += rsum[i]; Q += rsq[i]; }
        atomicAdd(&g_bn_s[c], S);
        atomicAdd(&g_bn_q[c], Q);
    }
}

// ---------------- deconv2 (smem-tiled) + loss write --------------------------
__global__ __launch_bounds__(512) void k_deconv2(const float* __restrict__ w,
                                                 const float* __restrict__ b,
                                                 const float* __restrict__ gamma,
                                                 const float* __restrict__ beta,
                                                 float* __restrict__ out,
                                                 int loss_idx){
    __shared__ ull   wp[256];
    __shared__ float w2[256];
    __shared__ float Asm[16], Bsm[16];
    float* tile = dynsm;
    int tid = threadIdx.x;
    if (tid < 256){
        wp[tid] = pack2(w[tid], w[256 + tid]);
        w2[tid] = w[512 + tid];
    }
    if (tid < 16){
        const float Nc = 32.f * 128.f * 128.f;
        float m = g_bn_s[tid] / Nc;
        float var = g_bn_q[tid] / Nc - m*m;
        float A = rsqrtf(var + EPSN) * gamma[tid];
        Asm[tid] = A;
        Bsm[tid] = fmaf(-m, A, beta[tid]);
    }
    if (blockIdx.x == 0 && tid == 0) out[loss_idx] = g_loss;
    __syncthreads();

    int n     = blockIdx.x >> 5;
    int chunk = blockIdx.x & 31;
    int ihg0 = chunk*4 - 1;
    const float* din = g_d1 + (size_t)n * 16 * 16384;
    for (int i = tid; i < 16*6*132; i += 512){
        int ci = i / 792, rem = i % 792;
        int rr = rem / 132, c = rem % 132;
        int ihg = ihg0 + rr, iwg = c - 1;
        float v = 0.f;
        if ((unsigned)ihg < 128u && (unsigned)iwg < 128u)
            v = fmaf(din[ci*16384 + ihg*128 + iwg], Asm[ci], Bsm[ci]);
        tile[i] = v;
    }
    __syncthreads();

    int rowl = tid >> 6, colA = tid & 63;
    int oh = chunk*8 + rowl;
    ull acc01[4];
    float acc2[4];
    #pragma unroll
    for (int px = 0; px < 4; px++){ acc01[px] = pack2(b[0], b[1]); acc2[px] = b[2]; }
    int p = rowl & 1, q = colA & 1;
    int lih0 = ((rowl + p - 2) >> 1) + 1;
    int lih1 = lih0 + 1;
    int liw0 = ((colA + q - 2) >> 1) + 1;
    const int i00 = p*4 + q, i01 = p*4 + q + 2, i10 = (p+2)*4 + q, i11 = (p+2)*4 + q + 2;
    for (int ci = 0; ci < 16; ci++){
        const float* tb = tile + ci*792;
        const float* r0 = tb + lih0*132;
        const float* r1 = tb + lih1*132;
        ull wa = wp[ci*16 + i00], wb = wp[ci*16 + i01];
        ull wc = wp[ci*16 + i10], wd = wp[ci*16 + i11];
        float s2a = w2[ci*16 + i00], s2b = w2[ci*16 + i01];
        float s2c = w2[ci*16 + i10], s2d = w2[ci*16 + i11];
        #pragma unroll
        for (int px = 0; px < 4; px++){
            int o = liw0 + px*32;
            float v00 = r0[o], v01 = r0[o+1];
            float v10 = r1[o], v11 = r1[o+1];
            FMA2(acc01[px], pack2(v00,v00), wa);
            FMA2(acc01[px], pack2(v01,v01), wb);
            FMA2(acc01[px], pack2(v10,v10), wc);
            FMA2(acc01[px], pack2(v11,v11), wd);
            acc2[px] = fmaf(v00, s2a, fmaf(v01, s2b, fmaf(v10, s2c, fmaf(v11, s2d, acc2[px]))));
        }
    }
    float* outp = out + (size_t)n * 3 * 65536 + oh*256 + colA;
    #pragma unroll
    for (int px = 0; px < 4; px++){
        float2 f01 = unpack2(acc01[px]);
        outp[px*64]          = f01.x;
        outp[px*64 + 65536]  = f01.y;
        outp[px*64 + 131072] = acc2[px];
    }
}

// ---------------- launch -----------------------------------------------------
extern "C" void kernel_launch(void* const* d_in, const int* in_sizes, int n_in,
                              void* d_out, int out_size){
    const float* x     = (const float*)d_in[0];
    const float* ew1   = (const float*)d_in[1];
    const float* eb1   = (const float*)d_in[2];
    const float* ew2   = (const float*)d_in[3];
    const float* eb2   = (const float*)d_in[4];
    const float* cb    = (const float*)d_in[5];
    const float* dw1   = (const float*)d_in[6];
    const float* db1   = (const float*)d_in[7];
    const float* gamma = (const float*)d_in[8];
    const float* beta  = (const float*)d_in[9];
    const float* dw2   = (const float*)d_in[10];
    const float* db2   = (const float*)d_in[11];
    float* out = (float*)d_out;

    const int conv2_smem   = (16384 + 16*18*132) * 4;
    const int deconv1_smem = (16384 + 64*6*68) * 4;
    const int deconv2_smem = (16*6*132) * 4;

    cudaFuncSetAttribute(k_conv2s,  cudaFuncAttributeMaxDynamicSharedMemorySize, conv2_smem);
    cudaFuncSetAttribute(k_rvq5,    cudaFuncAttributeMaxDynamicSharedMemorySize, RVQ5_SMEM);
    cudaFuncSetAttribute(k_deconv1, cudaFuncAttributeMaxDynamicSharedMemorySize, deconv1_smem);
    cudaFuncSetAttribute(k_deconv2, cudaFuncAttributeMaxDynamicSharedMemorySize, deconv2_smem);

    k_conv1x<<<512, 512>>>(x, ew1, eb1, cb);           // 1
    k_statsnorm<<<512, 512>>>(0);                      // 2
    k_conv2s<<<256, 512, conv2_smem>>>(ew2, eb2);      // 3
    k_rvq5<<<2048, 128, RVQ5_SMEM>>>(cb);              // 4
    k_deconv1<<<512, 512, deconv1_smem>>>(dw1, db1);   // 5
    k_bnstats<<<512, 256>>>();                         // 6
    k_deconv2<<<1024, 512, deconv2_smem>>>(dw2, db2, gamma, beta, out, out_size - 1); // 7
}